// round 14
// baseline (speedup 1.0000x reference)
#include <cuda_runtime.h>
#include <math.h>

#define S_    32
#define N_    128
#define NM1   127
#define D_    256
#define F_    516
#define TRI_  8128
#define M4    (S_*NM1)      // 4064
#define EDGES (S_*TRI_)     // 260096
#define EBLK  148

// ---------------- device scratch ----------------
__device__ __align__(16) float g_c0[D_];
__device__ __align__(16) float g_rnninp[M4*D_];
__device__ __align__(16) float g_ugi[M4*3*D_];
__device__ __align__(16) float g_mem[M4*D_];
__device__ __align__(16) float g_P[M4*D_];
__device__ __align__(16) float g_Q[M4*D_];
__device__ __align__(16) float g_hu[2][S_*D_];
__device__ __align__(16) float g_hd[2][S_*D_];
__device__ __align__(16) float g_part[EBLK*64];

__device__ __forceinline__ float sigf(float x) { return 1.f/(1.f+expf(-x)); }

// ---------------- init ----------------
__global__ void k_init() {
    int i = blockIdx.x*blockDim.x + threadIdx.x;
    if (i < S_*D_) { g_hu[0][i] = 0.f; g_hd[0][i] = 0.f; }
}

// ---------------- c0 = MLPReadout([z ; init]) ----------------
__global__ void k_c0(const float* __restrict__ z, const float* __restrict__ ip,
                     const float* __restrict__ W0, const float* __restrict__ b0,
                     const float* __restrict__ W1, const float* __restrict__ b1,
                     const float* __restrict__ W2, const float* __restrict__ b2)
{
    __shared__ float sin_[512];
    __shared__ float y0[256];
    __shared__ float y1[128];
    int tid = threadIdx.x;           // 256 threads
    sin_[tid]       = z[tid];
    sin_[256 + tid] = ip[tid];
    __syncthreads();
    float acc = b0[tid];
    for (int k = 0; k < 512; k++) acc += W0[tid*512 + k] * sin_[k];
    y0[tid] = fmaxf(acc, 0.f);
    __syncthreads();
    if (tid < 128) {
        float a = b1[tid];
        for (int k = 0; k < 256; k++) a += W1[tid*256 + k] * y0[k];
        y1[tid] = fmaxf(a, 0.f);
    }
    __syncthreads();
    float a2 = b2[tid];
    for (int k = 0; k < 128; k++) a2 += W2[tid*128 + k] * y1[k];
    g_c0[tid] = a2;
}

// ---------------- generic tiled GEMM: C = op(A @ B^T + bias) ----------------
// rowMode=1 maps GEMM row m -> x row (m + m/127 + 1)   (i.e. x[:, 1:])
__global__ void k_gemm(const float* __restrict__ A, int lda, int rowMode,
                       const float* __restrict__ B, int ldb,
                       const float* __restrict__ bias,
                       float* __restrict__ C, int ldc,
                       int M, int N, int K, int doRelu)
{
    __shared__ __align__(16) float As[16][68];
    __shared__ __align__(16) float Bs[16][68];
    int tid = threadIdx.x;                 // 256
    int bm = blockIdx.y * 64, bn = blockIdx.x * 64;
    int tx = tid & 15, ty = tid >> 4;
    int lr = tid >> 2, lc = (tid & 3) << 2;
    int am = bm + lr;
    long arow = -1;
    if (am < M) arow = rowMode ? (long)(am + am/NM1 + 1) : (long)am;
    int bnrow = bn + lr;
    float acc[4][4];
#pragma unroll
    for (int i = 0; i < 4; i++)
#pragma unroll
        for (int j = 0; j < 4; j++) acc[i][j] = 0.f;

    for (int k0 = 0; k0 < K; k0 += 16) {
#pragma unroll
        for (int i = 0; i < 4; i++) {
            int k = k0 + lc + i;
            As[lc+i][lr] = (arow >= 0 && k < K) ? A[arow*lda + k] : 0.f;
            Bs[lc+i][lr] = (bnrow < N && k < K) ? B[(long)bnrow*ldb + k] : 0.f;
        }
        __syncthreads();
#pragma unroll
        for (int k = 0; k < 16; k++) {
            float4 av = *(const float4*)&As[k][ty << 2];
            float4 bv = *(const float4*)&Bs[k][tx << 2];
            float a[4] = {av.x, av.y, av.z, av.w};
            float b[4] = {bv.x, bv.y, bv.z, bv.w};
#pragma unroll
            for (int i = 0; i < 4; i++)
#pragma unroll
                for (int j = 0; j < 4; j++) acc[i][j] += a[i]*b[j];
        }
        __syncthreads();
    }
#pragma unroll
    for (int i = 0; i < 4; i++) {
        int m = bm + (ty << 2) + i;
        if (m >= M) continue;
#pragma unroll
        for (int j = 0; j < 4; j++) {
            int n = bn + (tx << 2) + j;
            float v = acc[i][j] + (bias ? bias[n] : 0.f);
            if (doRelu) v = fmaxf(v, 0.f);
            C[(long)m*ldc + n] = v;
        }
    }
}

// ---------------- one coupled GRU time step ----------------
// blocks [0,32): update GRU (8 d-dims each); blocks [32,96): decoder GRU (4 d-dims each).
// Ping-pong state buffers on parity of t -> no cross-CTA races within a launch.
__global__ void k_step(int t,
    const float* __restrict__ uWhh, const float* __restrict__ ubhh,
    const float* __restrict__ dWih, const float* __restrict__ dbih,
    const float* __restrict__ dWhh, const float* __restrict__ dbhh)
{
    extern __shared__ __align__(16) float sm[];
    int tid = threadIdx.x;   // 256
    int b = blockIdx.x;
    int par = t & 1;

    if (b < 32) {
        int dbase = b << 3;
        float* sh = sm;          // 32 x 260
        float* sw = sm + 8320;   // 24 x 260
        const float4* hsrc = (const float4*)g_hu[par];
        float4* sh4 = (float4*)sh;
#pragma unroll
        for (int i = 0; i < 8; i++) {
            int fi = tid + (i << 8);
            int r = fi >> 6, k4 = fi & 63;
            sh4[r*65 + k4] = hsrc[fi];
        }
        const float4* wsrc = (const float4*)uWhh;
        float4* sw4 = (float4*)sw;
#pragma unroll
        for (int i = 0; i < 6; i++) {
            int fi = tid + (i << 8);
            int rr = fi >> 6, k4 = fi & 63;
            int g = rr >> 3, dl = rr & 7;
            sw4[rr*65 + k4] = wsrc[(g*256 + dbase + dl)*64 + k4];
        }
        __syncthreads();
        int s = tid >> 3, dl = tid & 7;
        int d = dbase + dl;
        const float4* hv = (const float4*)sh + s*65;
        const float4* w0 = (const float4*)sw + dl*65;
        const float4* w1 = w0 + 8*65;
        const float4* w2 = w0 + 16*65;
        float a0 = 0.f, a1 = 0.f, a2 = 0.f;
#pragma unroll 8
        for (int k = 0; k < 64; k++) {
            float4 h  = hv[k];
            float4 x0 = w0[k], x1 = w1[k], x2 = w2[k];
            a0 += h.x*x0.x + h.y*x0.y + h.z*x0.z + h.w*x0.w;
            a1 += h.x*x1.x + h.y*x1.y + h.z*x1.z + h.w*x1.w;
            a2 += h.x*x2.x + h.y*x2.y + h.z*x2.z + h.w*x2.w;
        }
        const float* gi = g_ugi + (long)(s*NM1 + t)*768;
        float r = sigf(gi[d]       + a0 + ubhh[d]);
        float z = sigf(gi[256 + d] + a1 + ubhh[256 + d]);
        float n = tanhf(gi[512 + d] + r*(a2 + ubhh[512 + d]));
        float ho = sh[s*260 + d];
        g_hu[par ^ 1][s*256 + d] = (1.f - z)*n + z*ho;
    } else {
        int b2 = b - 32;
        int dbase = b2 << 2;
        float* sinp = sm;             // 32 x 260
        float* shd  = sm + 8320;      // 32 x 260
        float* swi  = sm + 16640;     // 12 x 260
        float* swh  = sm + 19760;     // 12 x 260
        float* sx   = sm + 22880;     // 768
        float4* si4 = (float4*)sinp;
        float4* sd4 = (float4*)shd;
        const float4* hd4 = (const float4*)g_hd[par];
        if (t == 0) {
            const float4* c04 = (const float4*)g_c0;
#pragma unroll
            for (int i = 0; i < 8; i++) {
                int fi = tid + (i << 8);
                int r = fi >> 6, k4 = fi & 63;
                si4[r*65 + k4] = c04[k4];
                sd4[r*65 + k4] = hd4[fi];
            }
        } else {
            const float4* hu4 = (const float4*)g_hu[par];
#pragma unroll
            for (int i = 0; i < 8; i++) {
                int fi = tid + (i << 8);
                int r = fi >> 6, k4 = fi & 63;
                si4[r*65 + k4] = hu4[fi];
                sd4[r*65 + k4] = hd4[fi];
            }
        }
        const float4* wi4 = (const float4*)dWih;
        const float4* wh4 = (const float4*)dWhh;
        float4* swi4 = (float4*)swi;
        float4* swh4 = (float4*)swh;
#pragma unroll
        for (int i = 0; i < 3; i++) {
            int fi = tid + (i << 8);
            int rr = fi >> 6, k4 = fi & 63;
            int g = rr >> 2, dl = rr & 3;
            swi4[rr*65 + k4] = wi4[(g*256 + dbase + dl)*64 + k4];
            swh4[rr*65 + k4] = wh4[(g*256 + dbase + dl)*64 + k4];
        }
        __syncthreads();
        int s = tid >> 3;
        int rem = tid & 7;
        int dl = rem >> 1;
        int which = rem & 1;   // 0: input gates (gi), 1: hidden gates (gh)
        int d = dbase + dl;
        const float4* vec = (const float4*)(which ? shd : sinp) + s*65;
        const float4* wr0 = (const float4*)(which ? swh : swi) + dl*65;
        const float4* wr1 = wr0 + 4*65;
        const float4* wr2 = wr0 + 8*65;
        float a0 = 0.f, a1 = 0.f, a2 = 0.f;
#pragma unroll 8
        for (int k = 0; k < 64; k++) {
            float4 h  = vec[k];
            float4 x0 = wr0[k], x1 = wr1[k], x2 = wr2[k];
            a0 += h.x*x0.x + h.y*x0.y + h.z*x0.z + h.w*x0.w;
            a1 += h.x*x1.x + h.y*x1.y + h.z*x1.z + h.w*x1.w;
            a2 += h.x*x2.x + h.y*x2.y + h.z*x2.z + h.w*x2.w;
        }
        const float* bsrc = which ? dbhh : dbih;
        int xb = (s*4 + dl)*6 + which;
        sx[xb + 0] = a0 + bsrc[d];
        sx[xb + 2] = a1 + bsrc[256 + d];
        sx[xb + 4] = a2 + bsrc[512 + d];
        __syncthreads();
        if (which == 0) {
            int base = (s*4 + dl)*6;
            float r = sigf(sx[base+0] + sx[base+1]);
            float z = sigf(sx[base+2] + sx[base+3]);
            float n = tanhf(sx[base+4] + r*sx[base+5]);
            float ho = shd[s*260 + d];
            float hnew = (1.f - z)*n + z*ho;
            g_hd[par ^ 1][s*256 + d] = hnew;
            g_mem[(long)(s*NM1 + t)*256 + d] = hnew;
        }
    }
}

// ---------------- edge readout + BCE partial sums ----------------
__global__ void k_edge(const float* __restrict__ con,
                       const float* __restrict__ W1,
                       const float* __restrict__ b1,
                       const float* __restrict__ W2,
                       const float* __restrict__ b2)
{
    extern __shared__ __align__(16) float sm[];
    float* sW1  = sm;                 // 128 x 260 = 33280
    float* sh0  = sm + 33280;         // 32 x 260  = 8320
    float* sh1  = sm + 41600;         // 32 x 128  = 4096
    float* sW2  = sm + 45696;         // 256
    float* sb1  = sm + 45952;         // 128
    float* sb2v = sm + 46080;         // 4
    float* slog = sm + 46084;         // 64
    float* sacc = sm + 46148;         // 64
    float* sbce = sm + 46212;         // 64
    int*   sRP  = (int*)(sm + 46276); // 32
    int*   sRQ  = sRP + 32;           // 32
    int*   sS   = sRQ + 32;           // 32
    // total 46404 floats

    int tid = threadIdx.x; // 256
    {
        const float4* w4 = (const float4*)W1;
        float4* d4 = (float4*)sW1;
        for (int fi = tid; fi < 128*64; fi += 256) {
            int r = fi >> 6, k4 = fi & 63;
            d4[r*65 + k4] = w4[fi];
        }
    }
    sW2[tid] = W2[tid];
    if (tid < 128) sb1[tid] = b1[tid];
    if (tid < 2)   sb2v[tid] = b2[tid];
    if (tid < 64)  sacc[tid] = 0.f;
    __syncthreads();

    const float4* P4 = (const float4*)g_P;
    const float4* Q4 = (const float4*)g_Q;

    int per = (EDGES + gridDim.x - 1) / gridDim.x;
    int e0 = blockIdx.x * per;
    int e1 = min(e0 + per, EDGES);

    int eg  = tid & 7;
    int ogr = tid >> 3;

    for (int base = e0; base < e1; base += 32) {
        int nE = min(32, e1 - base);
        if (tid < nE) {
            int ge = base + tid;
            int s = ge / TRI_;
            int e = ge - s*TRI_;
            int i = (int)(0.5f*(sqrtf(8.f*(float)e + 1.f) - 1.f));
            while ((i+1)*(i+2)/2 <= e) ++i;
            while (i*(i+1)/2 > e)      --i;
            int j = e - i*(i+1)/2;
            sRP[tid] = (s*NM1 + j)*64;   // float4 row bases
            sRQ[tid] = (s*NM1 + i)*64;
            sS[tid] = s;
        }
        __syncthreads();
        // h0 = relu(P_j + Q_i)
        {
            float4* h04 = (float4*)sh0;
#pragma unroll
            for (int v = 0; v < 8; v++) {
                int fi = tid + (v << 8);
                int le = fi >> 6, k4 = fi & 63;
                float4 r;
                if (le < nE) {
                    float4 p = P4[sRP[le] + k4];
                    float4 q = Q4[sRQ[le] + k4];
                    r.x = fmaxf(p.x + q.x, 0.f);
                    r.y = fmaxf(p.y + q.y, 0.f);
                    r.z = fmaxf(p.z + q.z, 0.f);
                    r.w = fmaxf(p.w + q.w, 0.f);
                } else { r = make_float4(0.f, 0.f, 0.f, 0.f); }
                h04[le*65 + k4] = r;
            }
        }
        __syncthreads();
        // h1 = relu(h0 @ W1^T + b1): 4 edges x 4 outs per thread
        {
            float acc[4][4];
#pragma unroll
            for (int a = 0; a < 4; a++)
#pragma unroll
                for (int c = 0; c < 4; c++) acc[a][c] = 0.f;
            const float4* hv0 = (const float4*)sh0 + eg*65;
            const float4* wv0 = (const float4*)sW1 + ogr*65;
#pragma unroll 2
            for (int k = 0; k < 64; k++) {
                float4 h[4], w[4];
#pragma unroll
                for (int m = 0; m < 4; m++) h[m] = hv0[m*8*65 + k];
#pragma unroll
                for (int m = 0; m < 4; m++) w[m] = wv0[m*32*65 + k];
#pragma unroll
                for (int a = 0; a < 4; a++)
#pragma unroll
                    for (int c = 0; c < 4; c++)
                        acc[a][c] += h[a].x*w[c].x + h[a].y*w[c].y
                                   + h[a].z*w[c].z + h[a].w*w[c].w;
            }
#pragma unroll
            for (int a = 0; a < 4; a++) {
                int le = eg + a*8;
#pragma unroll
                for (int c = 0; c < 4; c++) {
                    int o = ogr + c*32;
                    sh1[le*128 + o] = fmaxf(acc[a][c] + sb1[o], 0.f);
                }
            }
        }
        __syncthreads();
        // logits
        if (tid < 64) {
            int le = tid >> 1, cls = tid & 1;
            float l = sb2v[cls];
            const float* hh = sh1 + le*128;
            const float* ww = sW2 + cls*128;
#pragma unroll 4
            for (int k = 0; k < 128; k++) l += hh[k]*ww[k];
            slog[le*2 + cls] = l;
        }
        __syncthreads();
        // softmax + clamped BCE (torch semantics)
        if (tid < nE) {
            int le = tid;
            float l0 = slog[le*2], l1 = slog[le*2 + 1];
            float mx = fmaxf(l0, l1);
            float ex0 = expf(l0 - mx), ex1 = expf(l1 - mx);
            float inv = 1.f/(ex0 + ex1);
            float p0 = ex0*inv, p1 = ex1*inv;
            float lg0 = fmaxf(logf(p0), -100.f);
            float lg1 = fmaxf(logf(p1), -100.f);
            float lm0 = fmaxf(log1pf(-p0), -100.f);
            float lm1 = fmaxf(log1pf(-p1), -100.f);
            int s = sS[le];
            const float* cp = con + ((long)s*TRI_ + ((long)(base + tid) - (long)s*TRI_))*2;
            float c0v = cp[0], c1v = cp[1];
            sbce[le*2 + 0] = -(c0v*lg0 + (1.f - c0v)*lm0);
            sbce[le*2 + 1] = -(c1v*lg1 + (1.f - c1v)*lm1);
        }
        __syncthreads();
        // deterministic per-block accumulation
        if (tid < 2) {
            for (int le = 0; le < nE; le++)
                sacc[sS[le]*2 + tid] += sbce[le*2 + tid];
        }
        __syncthreads();
    }
    if (tid < 64) g_part[blockIdx.x*64 + tid] = sacc[tid];
}

// ---------------- deterministic final reduction ----------------
__global__ void k_reduce(float* __restrict__ out) {
    int tid = threadIdx.x; // 64
    float a = 0.f;
    for (int b = 0; b < EBLK; b++) a += g_part[b*64 + tid];
    out[tid] = a;
}

extern "C" void kernel_launch(void* const* d_in, const int* in_sizes, int n_in,
                              void* d_out, int out_size) {
    const float* x       = (const float*)d_in[0];
    const float* con     = (const float*)d_in[1];
    const float* z_ph    = (const float*)d_in[2];
    const float* init_ph = (const float*)d_in[3];
    const float* cc_W0   = (const float*)d_in[4];
    const float* cc_b0   = (const float*)d_in[5];
    const float* cc_W1   = (const float*)d_in[6];
    const float* cc_b1   = (const float*)d_in[7];
    const float* cc_W2   = (const float*)d_in[8];
    const float* cc_b2   = (const float*)d_in[9];
    const float* er_W0   = (const float*)d_in[10];
    const float* er_b0   = (const float*)d_in[11];
    const float* er_W1   = (const float*)d_in[12];
    const float* er_b1   = (const float*)d_in[13];
    const float* er_W2   = (const float*)d_in[14];
    const float* er_b2   = (const float*)d_in[15];
    const float* rr_W    = (const float*)d_in[16];
    const float* rr_b    = (const float*)d_in[17];
    const float* dec_Wih = (const float*)d_in[18];
    const float* dec_Whh = (const float*)d_in[19];
    const float* dec_bih = (const float*)d_in[20];
    const float* dec_bhh = (const float*)d_in[21];
    const float* upd_Wih = (const float*)d_in[22];
    const float* upd_Whh = (const float*)d_in[23];
    const float* upd_bih = (const float*)d_in[24];
    const float* upd_bhh = (const float*)d_in[25];
    float* out = (float*)d_out;

    static bool attrs_done = false;
    if (!attrs_done) {
        cudaFuncSetAttribute(k_step, cudaFuncAttributeMaxDynamicSharedMemorySize, 23648*4);
        cudaFuncSetAttribute(k_edge, cudaFuncAttributeMaxDynamicSharedMemorySize, 46404*4);
        attrs_done = true;
    }

    k_init<<<32, 256>>>();
    k_c0<<<1, 256>>>(z_ph, init_ph, cc_W0, cc_b0, cc_W1, cc_b1, cc_W2, cc_b2);
    // rnninp = relu(x[:,1:] @ rr_W^T + rr_b)   (M=4064, N=256, K=516)
    k_gemm<<<dim3(4, 64), 256>>>(x, F_, 1, rr_W, F_, rr_b, g_rnninp, D_,
                                 M4, D_, F_, 1);
    // ugi = rnninp @ upd_Wih^T + upd_bih       (M=4064, N=768, K=256)
    k_gemm<<<dim3(12, 64), 256>>>(g_rnninp, D_, 0, upd_Wih, D_, upd_bih, g_ugi, 3*D_,
                                  M4, 3*D_, D_, 0);
    // coupled recurrence
    for (int t = 0; t < NM1; t++) {
        k_step<<<96, 256, 23648*4>>>(t, upd_Whh, upd_bhh,
                                     dec_Wih, dec_bih, dec_Whh, dec_bhh);
    }
    // P = mem @ W0a^T ; Q = mem @ W0b^T + b0   (er_W0 is (256, 512))
    k_gemm<<<dim3(4, 64), 256>>>(g_mem, D_, 0, er_W0, 2*D_, nullptr, g_P, D_,
                                 M4, D_, D_, 0);
    k_gemm<<<dim3(4, 64), 256>>>(g_mem, D_, 0, er_W0 + D_, 2*D_, er_b0, g_Q, D_,
                                 M4, D_, D_, 0);
    // edge MLP + BCE
    k_edge<<<EBLK, 256, 46404*4>>>(con, er_W1, er_b1, er_W2, er_b2);
    k_reduce<<<1, 64>>>(out);
}

// round 15
// speedup vs baseline: 1.1027x; 1.1027x over previous
#include <cuda_runtime.h>
#include <math.h>

#define S_    32
#define N_    128
#define NM1   127
#define D_    256
#define F_    516
#define TRI_  8128
#define M4    (S_*NM1)      // 4064
#define EDGES (S_*TRI_)     // 260096
#define EBLK  148
#define RBLK  96            // persistent recurrence CTAs (32 upd + 64 dec)

// ---------------- device scratch ----------------
__device__ __align__(16) float g_c0[D_];
__device__ __align__(16) float g_rnninp[M4*D_];
__device__ __align__(16) float g_ugi[M4*3*D_];
__device__ __align__(16) float g_mem[M4*D_];
__device__ __align__(16) float g_P[M4*D_];
__device__ __align__(16) float g_Q[M4*D_];
__device__ __align__(16) float g_hu[2][S_*D_];
__device__ __align__(16) float g_hd[2][S_*D_];
__device__ __align__(16) float g_part[EBLK*64];
__device__ int g_bar;

__device__ __forceinline__ float sigf(float x) { return 1.f/(1.f+expf(-x)); }

// ---------------- init ----------------
__global__ void k_init() {
    int i = blockIdx.x*blockDim.x + threadIdx.x;
    if (i < S_*D_) { g_hu[0][i] = 0.f; g_hd[0][i] = 0.f; }
    if (i == 0) g_bar = 0;
}

// ---------------- c0 = MLPReadout([z ; init]) ----------------
__global__ void k_c0(const float* __restrict__ z, const float* __restrict__ ip,
                     const float* __restrict__ W0, const float* __restrict__ b0,
                     const float* __restrict__ W1, const float* __restrict__ b1,
                     const float* __restrict__ W2, const float* __restrict__ b2)
{
    __shared__ float sin_[512];
    __shared__ float y0[256];
    __shared__ float y1[128];
    int tid = threadIdx.x;           // 256 threads
    sin_[tid]       = z[tid];
    sin_[256 + tid] = ip[tid];
    __syncthreads();
    float acc = b0[tid];
    for (int k = 0; k < 512; k++) acc += W0[tid*512 + k] * sin_[k];
    y0[tid] = fmaxf(acc, 0.f);
    __syncthreads();
    if (tid < 128) {
        float a = b1[tid];
        for (int k = 0; k < 256; k++) a += W1[tid*256 + k] * y0[k];
        y1[tid] = fmaxf(a, 0.f);
    }
    __syncthreads();
    float a2 = b2[tid];
    for (int k = 0; k < 128; k++) a2 += W2[tid*128 + k] * y1[k];
    g_c0[tid] = a2;
}

// ---------------- coalesced tiled GEMM: C = op(A @ B^T + bias) ----------------
// rowMode=1 maps GEMM row m -> x row (m + m/127 + 1)   (i.e. x[:, 1:])
__global__ void k_gemm(const float* __restrict__ A, int lda, int rowMode,
                       const float* __restrict__ B, int ldb,
                       const float* __restrict__ bias,
                       float* __restrict__ C, int ldc,
                       int M, int N, int K, int doRelu)
{
    __shared__ __align__(16) float As[16][68];
    __shared__ __align__(16) float Bs[16][68];
    int tid = threadIdx.x;                 // 256
    int bm = blockIdx.y * 64, bn = blockIdx.x * 64;
    int tx = tid & 15, ty = tid >> 4;
    int lrow = tid >> 2;                   // 0..63
    int lkq  = (tid & 3) << 2;             // k offset within tile (0,4,8,12)
    int am = bm + lrow;
    long arow = -1;
    if (am < M) arow = rowMode ? (long)(am + am/NM1 + 1) : (long)am;
    long brow = (long)(bn + lrow);         // always < N (N multiple of 64)
    float acc[4][4];
#pragma unroll
    for (int i = 0; i < 4; i++)
#pragma unroll
        for (int j = 0; j < 4; j++) acc[i][j] = 0.f;

    int ktiles = (K + 15) >> 4;
    for (int kt = 0; kt < ktiles; kt++) {
        int kk = (kt << 4) + lkq;
        float4 av, bv;
        if (kk + 3 < K) {
            av = (arow >= 0) ? *(const float4*)(A + arow*lda + kk)
                             : make_float4(0.f,0.f,0.f,0.f);
            bv = *(const float4*)(B + brow*ldb + kk);
        } else {
            float ta[4], tb[4];
#pragma unroll
            for (int i = 0; i < 4; i++) {
                int k = kk + i;
                ta[i] = (arow >= 0 && k < K) ? A[arow*lda + k] : 0.f;
                tb[i] = (k < K) ? B[brow*ldb + k] : 0.f;
            }
            av = make_float4(ta[0],ta[1],ta[2],ta[3]);
            bv = make_float4(tb[0],tb[1],tb[2],tb[3]);
        }
        As[lkq+0][lrow] = av.x; As[lkq+1][lrow] = av.y;
        As[lkq+2][lrow] = av.z; As[lkq+3][lrow] = av.w;
        Bs[lkq+0][lrow] = bv.x; Bs[lkq+1][lrow] = bv.y;
        Bs[lkq+2][lrow] = bv.z; Bs[lkq+3][lrow] = bv.w;
        __syncthreads();
#pragma unroll
        for (int k = 0; k < 16; k++) {
            float4 a4 = *(const float4*)&As[k][ty << 2];
            float4 b4 = *(const float4*)&Bs[k][tx << 2];
            float a[4] = {a4.x, a4.y, a4.z, a4.w};
            float b[4] = {b4.x, b4.y, b4.z, b4.w};
#pragma unroll
            for (int i = 0; i < 4; i++)
#pragma unroll
                for (int j = 0; j < 4; j++) acc[i][j] += a[i]*b[j];
        }
        __syncthreads();
    }
    int n0 = bn + (tx << 2);
    float bb[4] = {0.f,0.f,0.f,0.f};
    if (bias) { bb[0]=bias[n0]; bb[1]=bias[n0+1]; bb[2]=bias[n0+2]; bb[3]=bias[n0+3]; }
#pragma unroll
    for (int i = 0; i < 4; i++) {
        int m = bm + (ty << 2) + i;
        if (m >= M) continue;
        float4 v;
        v.x = acc[i][0] + bb[0]; v.y = acc[i][1] + bb[1];
        v.z = acc[i][2] + bb[2]; v.w = acc[i][3] + bb[3];
        if (doRelu) {
            v.x = fmaxf(v.x, 0.f); v.y = fmaxf(v.y, 0.f);
            v.z = fmaxf(v.z, 0.f); v.w = fmaxf(v.w, 0.f);
        }
        *(float4*)(C + (long)m*ldc + n0) = v;
    }
}

// ---------------- persistent coupled recurrence ----------------
// 96 CTAs, all resident (<=2 per SM). blocks [0,32): update GRU (8 d-dims);
// blocks [32,96): decoder GRU (4 d-dims). Software grid barrier between steps.
// State ping-pong uses __ldcg/__stcg (L2) to avoid stale L1 across CTAs.
__device__ __forceinline__ void gridbar(int target) {
    __syncthreads();
    if (threadIdx.x == 0) {
        __threadfence();
        atomicAdd(&g_bar, 1);
        volatile int* p = &g_bar;
        while (*p < target) { }
        __threadfence();
    }
    __syncthreads();
}

__global__ void __launch_bounds__(256, 2) k_recur(
    const float* __restrict__ uWhh, const float* __restrict__ ubhh,
    const float* __restrict__ dWih, const float* __restrict__ dbih,
    const float* __restrict__ dWhh, const float* __restrict__ dbhh)
{
    extern __shared__ __align__(16) float sm[];
    int tid = threadIdx.x;   // 256
    int b = blockIdx.x;

    if (b < 32) {
        // -------- update GRU: dims [dbase, dbase+8) for all 32 samples --------
        int dbase = b << 3;
        float* sh = sm;          // 32 x 260
        float* sw = sm + 8320;   // 24 x 260
        // load weight slice ONCE
        {
            const float4* wsrc = (const float4*)uWhh;
            float4* sw4 = (float4*)sw;
#pragma unroll
            for (int i = 0; i < 6; i++) {
                int fi = tid + (i << 8);
                int rr = fi >> 6, k4 = fi & 63;
                int g = rr >> 3, dl = rr & 7;
                sw4[rr*65 + k4] = wsrc[(g*256 + dbase + dl)*64 + k4];
            }
        }
        int s = tid >> 3, dl = tid & 7;
        int d = dbase + dl;
        float bh0 = ubhh[d], bh1 = ubhh[256 + d], bh2 = ubhh[512 + d];
        const float4* w0 = (const float4*)sw + dl*65;
        const float4* w1 = w0 + 8*65;
        const float4* w2 = w0 + 16*65;
        for (int t = 0; t < NM1; t++) {
            int par = t & 1;
            // stage h[par] into smem
            {
                const float4* hsrc = (const float4*)g_hu[par];
                float4* sh4 = (float4*)sh;
#pragma unroll
                for (int i = 0; i < 8; i++) {
                    int fi = tid + (i << 8);
                    int r = fi >> 6, k4 = fi & 63;
                    sh4[r*65 + k4] = __ldcg(hsrc + fi);
                }
            }
            __syncthreads();
            const float4* hv = (const float4*)sh + s*65;
            float a0 = 0.f, a1 = 0.f, a2 = 0.f;
#pragma unroll 8
            for (int k = 0; k < 64; k++) {
                float4 h  = hv[k];
                float4 x0 = w0[k], x1 = w1[k], x2 = w2[k];
                a0 += h.x*x0.x + h.y*x0.y + h.z*x0.z + h.w*x0.w;
                a1 += h.x*x1.x + h.y*x1.y + h.z*x1.z + h.w*x1.w;
                a2 += h.x*x2.x + h.y*x2.y + h.z*x2.z + h.w*x2.w;
            }
            const float* gi = g_ugi + (long)(s*NM1 + t)*768;
            float r = sigf(gi[d]       + a0 + bh0);
            float z = sigf(gi[256 + d] + a1 + bh1);
            float n = tanhf(gi[512 + d] + r*(a2 + bh2));
            float ho = sh[s*260 + d];
            __stcg(&g_hu[par ^ 1][s*256 + d], (1.f - z)*n + z*ho);
            if (t < NM1-1) gridbar((t+1)*RBLK); else { __syncthreads(); }
        }
    } else {
        // -------- decoder GRU: dims [dbase, dbase+4) for all 32 samples --------
        int b2 = b - 32;
        int dbase = b2 << 2;
        float* sinp = sm;             // 32 x 260
        float* shd  = sm + 8320;      // 32 x 260
        float* swi  = sm + 16640;     // 12 x 260
        float* swh  = sm + 19760;     // 12 x 260
        float* sx   = sm + 22880;     // 768
        // load weight slices ONCE
        {
            const float4* wi4 = (const float4*)dWih;
            const float4* wh4 = (const float4*)dWhh;
            float4* swi4 = (float4*)swi;
            float4* swh4 = (float4*)swh;
#pragma unroll
            for (int i = 0; i < 3; i++) {
                int fi = tid + (i << 8);
                int rr = fi >> 6, k4 = fi & 63;
                int g = rr >> 2, dl = rr & 3;
                swi4[rr*65 + k4] = wi4[(g*256 + dbase + dl)*64 + k4];
                swh4[rr*65 + k4] = wh4[(g*256 + dbase + dl)*64 + k4];
            }
        }
        int s = tid >> 3;
        int rem = tid & 7;
        int dl = rem >> 1;
        int which = rem & 1;   // 0: input gates, 1: hidden gates
        int d = dbase + dl;
        const float* bsrc = which ? dbhh : dbih;
        float bv0 = bsrc[d], bv1 = bsrc[256 + d], bv2 = bsrc[512 + d];
        const float4* wr0 = (const float4*)(which ? swh : swi) + dl*65;
        const float4* wr1 = wr0 + 4*65;
        const float4* wr2 = wr0 + 8*65;
        for (int t = 0; t < NM1; t++) {
            int par = t & 1;
            {
                float4* si4 = (float4*)sinp;
                float4* sd4 = (float4*)shd;
                const float4* hd4 = (const float4*)g_hd[par];
                if (t == 0) {
                    const float4* c04 = (const float4*)g_c0;
#pragma unroll
                    for (int i = 0; i < 8; i++) {
                        int fi = tid + (i << 8);
                        int r = fi >> 6, k4 = fi & 63;
                        si4[r*65 + k4] = c04[k4];
                        sd4[r*65 + k4] = __ldcg(hd4 + fi);
                    }
                } else {
                    const float4* hu4 = (const float4*)g_hu[par];
#pragma unroll
                    for (int i = 0; i < 8; i++) {
                        int fi = tid + (i << 8);
                        int r = fi >> 6, k4 = fi & 63;
                        si4[r*65 + k4] = __ldcg(hu4 + fi);
                        sd4[r*65 + k4] = __ldcg(hd4 + fi);
                    }
                }
            }
            __syncthreads();
            const float4* vec = (const float4*)(which ? shd : sinp) + s*65;
            float a0 = 0.f, a1 = 0.f, a2 = 0.f;
#pragma unroll 8
            for (int k = 0; k < 64; k++) {
                float4 h  = vec[k];
                float4 x0 = wr0[k], x1 = wr1[k], x2 = wr2[k];
                a0 += h.x*x0.x + h.y*x0.y + h.z*x0.z + h.w*x0.w;
                a1 += h.x*x1.x + h.y*x1.y + h.z*x1.z + h.w*x1.w;
                a2 += h.x*x2.x + h.y*x2.y + h.z*x2.z + h.w*x2.w;
            }
            int xb = (s*4 + dl)*6 + which;
            sx[xb + 0] = a0 + bv0;
            sx[xb + 2] = a1 + bv1;
            sx[xb + 4] = a2 + bv2;
            __syncthreads();
            if (which == 0) {
                int base = (s*4 + dl)*6;
                float r = sigf(sx[base+0] + sx[base+1]);
                float z = sigf(sx[base+2] + sx[base+3]);
                float n = tanhf(sx[base+4] + r*sx[base+5]);
                float ho = shd[s*260 + d];
                float hnew = (1.f - z)*n + z*ho;
                __stcg(&g_hd[par ^ 1][s*256 + d], hnew);
                g_mem[(long)(s*NM1 + t)*256 + d] = hnew;
            }
            if (t < NM1-1) gridbar((t+1)*RBLK); else { __syncthreads(); }
        }
    }
}

// ---------------- edge readout + BCE partial sums ----------------
__global__ void k_edge(const float* __restrict__ con,
                       const float* __restrict__ W1,
                       const float* __restrict__ b1,
                       const float* __restrict__ W2,
                       const float* __restrict__ b2)
{
    extern __shared__ __align__(16) float sm[];
    float* sW1  = sm;                 // 128 x 260 = 33280
    float* sh0  = sm + 33280;         // 32 x 260  = 8320
    float* sh1  = sm + 41600;         // 32 x 128  = 4096
    float* sW2  = sm + 45696;         // 256
    float* sb1  = sm + 45952;         // 128
    float* sb2v = sm + 46080;         // 4
    float* slog = sm + 46084;         // 64
    float* sacc = sm + 46148;         // 64
    float* sbce = sm + 46212;         // 64
    int*   sRP  = (int*)(sm + 46276); // 32
    int*   sRQ  = sRP + 32;           // 32
    int*   sS   = sRQ + 32;           // 32

    int tid = threadIdx.x; // 256
    {
        const float4* w4 = (const float4*)W1;
        float4* d4 = (float4*)sW1;
        for (int fi = tid; fi < 128*64; fi += 256) {
            int r = fi >> 6, k4 = fi & 63;
            d4[r*65 + k4] = w4[fi];
        }
    }
    sW2[tid] = W2[tid];
    if (tid < 128) sb1[tid] = b1[tid];
    if (tid < 2)   sb2v[tid] = b2[tid];
    if (tid < 64)  sacc[tid] = 0.f;
    __syncthreads();

    const float4* P4 = (const float4*)g_P;
    const float4* Q4 = (const float4*)g_Q;

    int per = (EDGES + gridDim.x - 1) / gridDim.x;
    int e0 = blockIdx.x * per;
    int e1 = min(e0 + per, EDGES);

    int eg  = tid & 7;
    int ogr = tid >> 3;

    for (int base = e0; base < e1; base += 32) {
        int nE = min(32, e1 - base);
        if (tid < nE) {
            int ge = base + tid;
            int s = ge / TRI_;
            int e = ge - s*TRI_;
            int i = (int)(0.5f*(sqrtf(8.f*(float)e + 1.f) - 1.f));
            while ((i+1)*(i+2)/2 <= e) ++i;
            while (i*(i+1)/2 > e)      --i;
            int j = e - i*(i+1)/2;
            sRP[tid] = (s*NM1 + j)*64;   // float4 row bases
            sRQ[tid] = (s*NM1 + i)*64;
            sS[tid] = s;
        }
        __syncthreads();
        // h0 = relu(P_j + Q_i)
        {
            float4* h04 = (float4*)sh0;
#pragma unroll
            for (int v = 0; v < 8; v++) {
                int fi = tid + (v << 8);
                int le = fi >> 6, k4 = fi & 63;
                float4 r;
                if (le < nE) {
                    float4 p = P4[sRP[le] + k4];
                    float4 q = Q4[sRQ[le] + k4];
                    r.x = fmaxf(p.x + q.x, 0.f);
                    r.y = fmaxf(p.y + q.y, 0.f);
                    r.z = fmaxf(p.z + q.z, 0.f);
                    r.w = fmaxf(p.w + q.w, 0.f);
                } else { r = make_float4(0.f, 0.f, 0.f, 0.f); }
                h04[le*65 + k4] = r;
            }
        }
        __syncthreads();
        // h1 = relu(h0 @ W1^T + b1): 4 edges x 4 outs per thread
        {
            float acc[4][4];
#pragma unroll
            for (int a = 0; a < 4; a++)
#pragma unroll
                for (int c = 0; c < 4; c++) acc[a][c] = 0.f;
            const float4* hv0 = (const float4*)sh0 + eg*65;
            const float4* wv0 = (const float4*)sW1 + ogr*65;
#pragma unroll 2
            for (int k = 0; k < 64; k++) {
                float4 h[4], w[4];
#pragma unroll
                for (int m = 0; m < 4; m++) h[m] = hv0[m*8*65 + k];
#pragma unroll
                for (int m = 0; m < 4; m++) w[m] = wv0[m*32*65 + k];
#pragma unroll
                for (int a = 0; a < 4; a++)
#pragma unroll
                    for (int c = 0; c < 4; c++)
                        acc[a][c] += h[a].x*w[c].x + h[a].y*w[c].y
                                   + h[a].z*w[c].z + h[a].w*w[c].w;
            }
#pragma unroll
            for (int a = 0; a < 4; a++) {
                int le = eg + a*8;
#pragma unroll
                for (int c = 0; c < 4; c++) {
                    int o = ogr + c*32;
                    sh1[le*128 + o] = fmaxf(acc[a][c] + sb1[o], 0.f);
                }
            }
        }
        __syncthreads();
        // logits
        if (tid < 64) {
            int le = tid >> 1, cls = tid & 1;
            float l = sb2v[cls];
            const float* hh = sh1 + le*128;
            const float* ww = sW2 + cls*128;
#pragma unroll 4
            for (int k = 0; k < 128; k++) l += hh[k]*ww[k];
            slog[le*2 + cls] = l;
        }
        __syncthreads();
        // softmax + clamped BCE (torch semantics)
        if (tid < nE) {
            int le = tid;
            float l0 = slog[le*2], l1 = slog[le*2 + 1];
            float mx = fmaxf(l0, l1);
            float ex0 = expf(l0 - mx), ex1 = expf(l1 - mx);
            float inv = 1.f/(ex0 + ex1);
            float p0 = ex0*inv, p1 = ex1*inv;
            float lg0 = fmaxf(logf(p0), -100.f);
            float lg1 = fmaxf(logf(p1), -100.f);
            float lm0 = fmaxf(log1pf(-p0), -100.f);
            float lm1 = fmaxf(log1pf(-p1), -100.f);
            int s = sS[le];
            const float* cp = con + (long)(base + tid)*2;
            float c0v = cp[0], c1v = cp[1];
            sbce[le*2 + 0] = -(c0v*lg0 + (1.f - c0v)*lm0);
            sbce[le*2 + 1] = -(c1v*lg1 + (1.f - c1v)*lm1);
        }
        __syncthreads();
        if (tid < 2) {
            for (int le = 0; le < nE; le++)
                sacc[sS[le]*2 + tid] += sbce[le*2 + tid];
        }
        __syncthreads();
    }
    if (tid < 64) g_part[blockIdx.x*64 + tid] = sacc[tid];
}

// ---------------- deterministic final reduction ----------------
__global__ void k_reduce(float* __restrict__ out) {
    int tid = threadIdx.x; // 64
    float a = 0.f;
    for (int b = 0; b < EBLK; b++) a += g_part[b*64 + tid];
    out[tid] = a;
}

extern "C" void kernel_launch(void* const* d_in, const int* in_sizes, int n_in,
                              void* d_out, int out_size) {
    const float* x       = (const float*)d_in[0];
    const float* con     = (const float*)d_in[1];
    const float* z_ph    = (const float*)d_in[2];
    const float* init_ph = (const float*)d_in[3];
    const float* cc_W0   = (const float*)d_in[4];
    const float* cc_b0   = (const float*)d_in[5];
    const float* cc_W1   = (const float*)d_in[6];
    const float* cc_b1   = (const float*)d_in[7];
    const float* cc_W2   = (const float*)d_in[8];
    const float* cc_b2   = (const float*)d_in[9];
    const float* er_W0   = (const float*)d_in[10];
    const float* er_b0   = (const float*)d_in[11];
    const float* er_W1   = (const float*)d_in[12];
    const float* er_b1   = (const float*)d_in[13];
    const float* er_W2   = (const float*)d_in[14];
    const float* er_b2   = (const float*)d_in[15];
    const float* rr_W    = (const float*)d_in[16];
    const float* rr_b    = (const float*)d_in[17];
    const float* dec_Wih = (const float*)d_in[18];
    const float* dec_Whh = (const float*)d_in[19];
    const float* dec_bih = (const float*)d_in[20];
    const float* dec_bhh = (const float*)d_in[21];
    const float* upd_Wih = (const float*)d_in[22];
    const float* upd_Whh = (const float*)d_in[23];
    const float* upd_bih = (const float*)d_in[24];
    const float* upd_bhh = (const float*)d_in[25];
    float* out = (float*)d_out;

    cudaFuncSetAttribute(k_recur, cudaFuncAttributeMaxDynamicSharedMemorySize, 23648*4);
    cudaFuncSetAttribute(k_edge,  cudaFuncAttributeMaxDynamicSharedMemorySize, 46404*4);

    k_init<<<32, 256>>>();
    k_c0<<<1, 256>>>(z_ph, init_ph, cc_W0, cc_b0, cc_W1, cc_b1, cc_W2, cc_b2);
    // rnninp = relu(x[:,1:] @ rr_W^T + rr_b)   (M=4064, N=256, K=516)
    k_gemm<<<dim3(4, 64), 256>>>(x, F_, 1, rr_W, F_, rr_b, g_rnninp, D_,
                                 M4, D_, F_, 1);
    // ugi = rnninp @ upd_Wih^T + upd_bih       (M=4064, N=768, K=256)
    k_gemm<<<dim3(12, 64), 256>>>(g_rnninp, D_, 0, upd_Wih, D_, upd_bih, g_ugi, 3*D_,
                                  M4, 3*D_, D_, 0);
    // persistent coupled recurrence (127 steps, 1 launch)
    k_recur<<<RBLK, 256, 23648*4>>>(upd_Whh, upd_bhh,
                                    dec_Wih, dec_bih, dec_Whh, dec_bhh);
    // P = mem @ W0a^T ; Q = mem @ W0b^T + b0   (er_W0 is (256, 512))
    k_gemm<<<dim3(4, 64), 256>>>(g_mem, D_, 0, er_W0, 2*D_, nullptr, g_P, D_,
                                 M4, D_, D_, 0);
    k_gemm<<<dim3(4, 64), 256>>>(g_mem, D_, 0, er_W0 + D_, 2*D_, er_b0, g_Q, D_,
                                 M4, D_, D_, 0);
    // edge MLP + BCE
    k_edge<<<EBLK, 256, 46404*4>>>(con, er_W1, er_b1, er_W2, er_b2);
    k_reduce<<<1, 64>>>(out);
}

// round 16
// speedup vs baseline: 1.1061x; 1.0030x over previous
#include <cuda_runtime.h>
#include <math.h>

#define S_    32
#define N_    128
#define NM1   127
#define D_    256
#define F_    516
#define TRI_  8128
#define M4    (S_*NM1)      // 4064
#define EDGES (S_*TRI_)     // 260096
#define EBLK  148
#define RBLK  96            // persistent recurrence CTAs (32 upd + 64 dec)

// ---------------- device scratch ----------------
__device__ __align__(16) float g_c0[D_];
__device__ __align__(16) float g_rnninp[M4*D_];
__device__ __align__(16) float g_ugi[M4*3*D_];
__device__ __align__(16) float g_mem[M4*D_];
__device__ __align__(16) float g_P[M4*D_];
__device__ __align__(16) float g_Q[M4*D_];
__device__ __align__(16) float g_hu[2][S_*D_];
__device__ __align__(16) float g_hd[2][S_*D_];
__device__ __align__(16) float g_part[EBLK*64];
__device__ int g_bar;

__device__ __forceinline__ float sigf(float x) { return 1.f/(1.f+expf(-x)); }

// ---------------- init ----------------
__global__ void k_init() {
    int i = blockIdx.x*blockDim.x + threadIdx.x;
    if (i < S_*D_) { g_hu[0][i] = 0.f; g_hd[0][i] = 0.f; }
    if (i == 0) g_bar = 0;
}

// ---------------- c0 = MLPReadout([z ; init]) ----------------
__global__ void k_c0(const float* __restrict__ z, const float* __restrict__ ip,
                     const float* __restrict__ W0, const float* __restrict__ b0,
                     const float* __restrict__ W1, const float* __restrict__ b1,
                     const float* __restrict__ W2, const float* __restrict__ b2)
{
    __shared__ float sin_[512];
    __shared__ float y0[256];
    __shared__ float y1[128];
    int tid = threadIdx.x;           // 256 threads
    sin_[tid]       = z[tid];
    sin_[256 + tid] = ip[tid];
    __syncthreads();
    float acc = b0[tid];
    for (int k = 0; k < 512; k++) acc += W0[tid*512 + k] * sin_[k];
    y0[tid] = fmaxf(acc, 0.f);
    __syncthreads();
    if (tid < 128) {
        float a = b1[tid];
        for (int k = 0; k < 256; k++) a += W1[tid*256 + k] * y0[k];
        y1[tid] = fmaxf(a, 0.f);
    }
    __syncthreads();
    float a2 = b2[tid];
    for (int k = 0; k < 128; k++) a2 += W2[tid*128 + k] * y1[k];
    g_c0[tid] = a2;
}

// ---------------- double-buffered tiled GEMM: C = op(A @ B^T + bias) ----------
// rowMode=1 maps GEMM row m -> x row (m + m/127 + 1)   (i.e. x[:, 1:])
__global__ void k_gemm(const float* __restrict__ A, int lda, int rowMode,
                       const float* __restrict__ B, int ldb,
                       const float* __restrict__ bias,
                       float* __restrict__ C, int ldc,
                       int M, int N, int K, int doRelu)
{
    __shared__ __align__(16) float As[2][16][68];
    __shared__ __align__(16) float Bs[2][16][68];
    int tid = threadIdx.x;                 // 256
    int bm = blockIdx.y * 64, bn = blockIdx.x * 64;
    int tx = tid & 15, ty = tid >> 4;
    int lrow = tid >> 2;                   // 0..63
    int lkq  = (tid & 3) << 2;             // k offset within tile (0,4,8,12)
    int am = bm + lrow;
    long arow = -1;
    if (am < M) arow = rowMode ? (long)(am + am/NM1 + 1) : (long)am;
    long brow = (long)(bn + lrow);         // always < N (N multiple of 64)
    float acc[4][4];
#pragma unroll
    for (int i = 0; i < 4; i++)
#pragma unroll
        for (int j = 0; j < 4; j++) acc[i][j] = 0.f;

    int ktiles = (K + 15) >> 4;
    float4 av, bv;

    // prefetch tile 0
    {
        int kk = lkq;
        if (kk + 3 < K) {
            av = (arow >= 0) ? *(const float4*)(A + arow*lda + kk)
                             : make_float4(0.f,0.f,0.f,0.f);
            bv = *(const float4*)(B + brow*ldb + kk);
        } else {
            float ta[4], tb[4];
#pragma unroll
            for (int i = 0; i < 4; i++) {
                int k = kk + i;
                ta[i] = (arow >= 0 && k < K) ? A[arow*lda + k] : 0.f;
                tb[i] = (k < K) ? B[brow*ldb + k] : 0.f;
            }
            av = make_float4(ta[0],ta[1],ta[2],ta[3]);
            bv = make_float4(tb[0],tb[1],tb[2],tb[3]);
        }
        As[0][lkq+0][lrow] = av.x; As[0][lkq+1][lrow] = av.y;
        As[0][lkq+2][lrow] = av.z; As[0][lkq+3][lrow] = av.w;
        Bs[0][lkq+0][lrow] = bv.x; Bs[0][lkq+1][lrow] = bv.y;
        Bs[0][lkq+2][lrow] = bv.z; Bs[0][lkq+3][lrow] = bv.w;
    }
    __syncthreads();

    for (int kt = 0; kt < ktiles; kt++) {
        int cur = kt & 1, nxt = cur ^ 1;
        bool have_next = (kt + 1 < ktiles);
        if (have_next) {
            int kk = ((kt + 1) << 4) + lkq;
            if (kk + 3 < K) {
                av = (arow >= 0) ? *(const float4*)(A + arow*lda + kk)
                                 : make_float4(0.f,0.f,0.f,0.f);
                bv = *(const float4*)(B + brow*ldb + kk);
            } else {
                float ta[4], tb[4];
#pragma unroll
                for (int i = 0; i < 4; i++) {
                    int k = kk + i;
                    ta[i] = (arow >= 0 && k < K) ? A[arow*lda + k] : 0.f;
                    tb[i] = (k < K) ? B[brow*ldb + k] : 0.f;
                }
                av = make_float4(ta[0],ta[1],ta[2],ta[3]);
                bv = make_float4(tb[0],tb[1],tb[2],tb[3]);
            }
        }
#pragma unroll
        for (int k = 0; k < 16; k++) {
            float4 a4 = *(const float4*)&As[cur][k][ty << 2];
            float4 b4 = *(const float4*)&Bs[cur][k][tx << 2];
            float a[4] = {a4.x, a4.y, a4.z, a4.w};
            float b[4] = {b4.x, b4.y, b4.z, b4.w};
#pragma unroll
            for (int i = 0; i < 4; i++)
#pragma unroll
                for (int j = 0; j < 4; j++) acc[i][j] += a[i]*b[j];
        }
        if (have_next) {
            As[nxt][lkq+0][lrow] = av.x; As[nxt][lkq+1][lrow] = av.y;
            As[nxt][lkq+2][lrow] = av.z; As[nxt][lkq+3][lrow] = av.w;
            Bs[nxt][lkq+0][lrow] = bv.x; Bs[nxt][lkq+1][lrow] = bv.y;
            Bs[nxt][lkq+2][lrow] = bv.z; Bs[nxt][lkq+3][lrow] = bv.w;
            __syncthreads();
        }
    }
    int n0 = bn + (tx << 2);
    float bb[4] = {0.f,0.f,0.f,0.f};
    if (bias) { bb[0]=bias[n0]; bb[1]=bias[n0+1]; bb[2]=bias[n0+2]; bb[3]=bias[n0+3]; }
#pragma unroll
    for (int i = 0; i < 4; i++) {
        int m = bm + (ty << 2) + i;
        if (m >= M) continue;
        float4 v;
        v.x = acc[i][0] + bb[0]; v.y = acc[i][1] + bb[1];
        v.z = acc[i][2] + bb[2]; v.w = acc[i][3] + bb[3];
        if (doRelu) {
            v.x = fmaxf(v.x, 0.f); v.y = fmaxf(v.y, 0.f);
            v.z = fmaxf(v.z, 0.f); v.w = fmaxf(v.w, 0.f);
        }
        *(float4*)(C + (long)m*ldc + n0) = v;
    }
}

// ---------------- persistent coupled recurrence ----------------
__device__ __forceinline__ void gridbar(int target) {
    __syncthreads();
    if (threadIdx.x == 0) {
        __threadfence();
        atomicAdd(&g_bar, 1);
        volatile int* p = &g_bar;
        while (*p < target) { }
        __threadfence();
    }
    __syncthreads();
}

__global__ void __launch_bounds__(256, 2) k_recur(
    const float* __restrict__ uWhh, const float* __restrict__ ubhh,
    const float* __restrict__ dWih, const float* __restrict__ dbih,
    const float* __restrict__ dWhh, const float* __restrict__ dbhh)
{
    extern __shared__ __align__(16) float sm[];
    int tid = threadIdx.x;   // 256
    int b = blockIdx.x;

    if (b < 32) {
        int dbase = b << 3;
        float* sh = sm;          // 32 x 260
        float* sw = sm + 8320;   // 24 x 260
        {
            const float4* wsrc = (const float4*)uWhh;
            float4* sw4 = (float4*)sw;
#pragma unroll
            for (int i = 0; i < 6; i++) {
                int fi = tid + (i << 8);
                int rr = fi >> 6, k4 = fi & 63;
                int g = rr >> 3, dl = rr & 7;
                sw4[rr*65 + k4] = wsrc[(g*256 + dbase + dl)*64 + k4];
            }
        }
        int s = tid >> 3, dl = tid & 7;
        int d = dbase + dl;
        float bh0 = ubhh[d], bh1 = ubhh[256 + d], bh2 = ubhh[512 + d];
        const float4* w0 = (const float4*)sw + dl*65;
        const float4* w1 = w0 + 8*65;
        const float4* w2 = w0 + 16*65;
        for (int t = 0; t < NM1; t++) {
            int par = t & 1;
            {
                const float4* hsrc = (const float4*)g_hu[par];
                float4* sh4 = (float4*)sh;
#pragma unroll
                for (int i = 0; i < 8; i++) {
                    int fi = tid + (i << 8);
                    int r = fi >> 6, k4 = fi & 63;
                    sh4[r*65 + k4] = __ldcg(hsrc + fi);
                }
            }
            __syncthreads();
            const float4* hv = (const float4*)sh + s*65;
            float a0 = 0.f, a1 = 0.f, a2 = 0.f;
#pragma unroll 8
            for (int k = 0; k < 64; k++) {
                float4 h  = hv[k];
                float4 x0 = w0[k], x1 = w1[k], x2 = w2[k];
                a0 += h.x*x0.x + h.y*x0.y + h.z*x0.z + h.w*x0.w;
                a1 += h.x*x1.x + h.y*x1.y + h.z*x1.z + h.w*x1.w;
                a2 += h.x*x2.x + h.y*x2.y + h.z*x2.z + h.w*x2.w;
            }
            const float* gi = g_ugi + (long)(s*NM1 + t)*768;
            float r = sigf(gi[d]       + a0 + bh0);
            float z = sigf(gi[256 + d] + a1 + bh1);
            float n = tanhf(gi[512 + d] + r*(a2 + bh2));
            float ho = sh[s*260 + d];
            __stcg(&g_hu[par ^ 1][s*256 + d], (1.f - z)*n + z*ho);
            if (t < NM1-1) gridbar((t+1)*RBLK); else { __syncthreads(); }
        }
    } else {
        int b2 = b - 32;
        int dbase = b2 << 2;
        float* sinp = sm;             // 32 x 260
        float* shd  = sm + 8320;      // 32 x 260
        float* swi  = sm + 16640;     // 12 x 260
        float* swh  = sm + 19760;     // 12 x 260
        float* sx   = sm + 22880;     // 768
        {
            const float4* wi4 = (const float4*)dWih;
            const float4* wh4 = (const float4*)dWhh;
            float4* swi4 = (float4*)swi;
            float4* swh4 = (float4*)swh;
#pragma unroll
            for (int i = 0; i < 3; i++) {
                int fi = tid + (i << 8);
                int rr = fi >> 6, k4 = fi & 63;
                int g = rr >> 2, dl = rr & 3;
                swi4[rr*65 + k4] = wi4[(g*256 + dbase + dl)*64 + k4];
                swh4[rr*65 + k4] = wh4[(g*256 + dbase + dl)*64 + k4];
            }
        }
        int s = tid >> 3;
        int rem = tid & 7;
        int dl = rem >> 1;
        int which = rem & 1;   // 0: input gates, 1: hidden gates
        int d = dbase + dl;
        const float* bsrc = which ? dbhh : dbih;
        float bv0 = bsrc[d], bv1 = bsrc[256 + d], bv2 = bsrc[512 + d];
        const float4* wr0 = (const float4*)(which ? swh : swi) + dl*65;
        const float4* wr1 = wr0 + 4*65;
        const float4* wr2 = wr0 + 8*65;
        for (int t = 0; t < NM1; t++) {
            int par = t & 1;
            {
                float4* si4 = (float4*)sinp;
                float4* sd4 = (float4*)shd;
                const float4* hd4 = (const float4*)g_hd[par];
                if (t == 0) {
                    const float4* c04 = (const float4*)g_c0;
#pragma unroll
                    for (int i = 0; i < 8; i++) {
                        int fi = tid + (i << 8);
                        int r = fi >> 6, k4 = fi & 63;
                        si4[r*65 + k4] = c04[k4];
                        sd4[r*65 + k4] = __ldcg(hd4 + fi);
                    }
                } else {
                    const float4* hu4 = (const float4*)g_hu[par];
#pragma unroll
                    for (int i = 0; i < 8; i++) {
                        int fi = tid + (i << 8);
                        int r = fi >> 6, k4 = fi & 63;
                        si4[r*65 + k4] = __ldcg(hu4 + fi);
                        sd4[r*65 + k4] = __ldcg(hd4 + fi);
                    }
                }
            }
            __syncthreads();
            const float4* vec = (const float4*)(which ? shd : sinp) + s*65;
            float a0 = 0.f, a1 = 0.f, a2 = 0.f;
#pragma unroll 8
            for (int k = 0; k < 64; k++) {
                float4 h  = vec[k];
                float4 x0 = wr0[k], x1 = wr1[k], x2 = wr2[k];
                a0 += h.x*x0.x + h.y*x0.y + h.z*x0.z + h.w*x0.w;
                a1 += h.x*x1.x + h.y*x1.y + h.z*x1.z + h.w*x1.w;
                a2 += h.x*x2.x + h.y*x2.y + h.z*x2.z + h.w*x2.w;
            }
            int xb = (s*4 + dl)*6 + which;
            sx[xb + 0] = a0 + bv0;
            sx[xb + 2] = a1 + bv1;
            sx[xb + 4] = a2 + bv2;
            __syncthreads();
            if (which == 0) {
                int base = (s*4 + dl)*6;
                float r = sigf(sx[base+0] + sx[base+1]);
                float z = sigf(sx[base+2] + sx[base+3]);
                float n = tanhf(sx[base+4] + r*sx[base+5]);
                float ho = shd[s*260 + d];
                float hnew = (1.f - z)*n + z*ho;
                __stcg(&g_hd[par ^ 1][s*256 + d], hnew);
                g_mem[(long)(s*NM1 + t)*256 + d] = hnew;
            }
            if (t < NM1-1) gridbar((t+1)*RBLK); else { __syncthreads(); }
        }
    }
}

// ---------------- edge readout + BCE partial sums ----------------
__global__ void k_edge(const float* __restrict__ con,
                       const float* __restrict__ W1,
                       const float* __restrict__ b1,
                       const float* __restrict__ W2,
                       const float* __restrict__ b2)
{
    extern __shared__ __align__(16) float sm[];
    float* sW1  = sm;                 // 128 x 260 = 33280
    float* sh0  = sm + 33280;         // 32 x 260  = 8320
    float* sh1  = sm + 41600;         // 32 x 128  = 4096
    float* sW2  = sm + 45696;         // 256
    float* sb1  = sm + 45952;         // 128
    float* sb2v = sm + 46080;         // 4
    float* slog = sm + 46084;         // 64
    float* sacc = sm + 46148;         // 64
    float* sbce = sm + 46212;         // 64
    int*   sRP  = (int*)(sm + 46276); // 32
    int*   sRQ  = sRP + 32;           // 32
    int*   sS   = sRQ + 32;           // 32

    int tid = threadIdx.x; // 256
    {
        const float4* w4 = (const float4*)W1;
        float4* d4 = (float4*)sW1;
        for (int fi = tid; fi < 128*64; fi += 256) {
            int r = fi >> 6, k4 = fi & 63;
            d4[r*65 + k4] = w4[fi];
        }
    }
    sW2[tid] = W2[tid];
    if (tid < 128) sb1[tid] = b1[tid];
    if (tid < 2)   sb2v[tid] = b2[tid];
    if (tid < 64)  sacc[tid] = 0.f;
    __syncthreads();

    const float4* P4 = (const float4*)g_P;
    const float4* Q4 = (const float4*)g_Q;

    int per = (EDGES + gridDim.x - 1) / gridDim.x;
    int e0 = blockIdx.x * per;
    int e1 = min(e0 + per, EDGES);

    int eg  = tid & 7;
    int ogr = tid >> 3;

    for (int base = e0; base < e1; base += 32) {
        int nE = min(32, e1 - base);
        if (tid < nE) {
            int ge = base + tid;
            int s = ge / TRI_;
            int e = ge - s*TRI_;
            int i = (int)(0.5f*(sqrtf(8.f*(float)e + 1.f) - 1.f));
            while ((i+1)*(i+2)/2 <= e) ++i;
            while (i*(i+1)/2 > e)      --i;
            int j = e - i*(i+1)/2;
            sRP[tid] = (s*NM1 + j)*64;   // float4 row bases
            sRQ[tid] = (s*NM1 + i)*64;
            sS[tid] = s;
        }
        __syncthreads();
        {
            float4* h04 = (float4*)sh0;
#pragma unroll
            for (int v = 0; v < 8; v++) {
                int fi = tid + (v << 8);
                int le = fi >> 6, k4 = fi & 63;
                float4 r;
                if (le < nE) {
                    float4 p = P4[sRP[le] + k4];
                    float4 q = Q4[sRQ[le] + k4];
                    r.x = fmaxf(p.x + q.x, 0.f);
                    r.y = fmaxf(p.y + q.y, 0.f);
                    r.z = fmaxf(p.z + q.z, 0.f);
                    r.w = fmaxf(p.w + q.w, 0.f);
                } else { r = make_float4(0.f, 0.f, 0.f, 0.f); }
                h04[le*65 + k4] = r;
            }
        }
        __syncthreads();
        {
            float acc[4][4];
#pragma unroll
            for (int a = 0; a < 4; a++)
#pragma unroll
                for (int c = 0; c < 4; c++) acc[a][c] = 0.f;
            const float4* hv0 = (const float4*)sh0 + eg*65;
            const float4* wv0 = (const float4*)sW1 + ogr*65;
#pragma unroll 2
            for (int k = 0; k < 64; k++) {
                float4 h[4], w[4];
#pragma unroll
                for (int m = 0; m < 4; m++) h[m] = hv0[m*8*65 + k];
#pragma unroll
                for (int m = 0; m < 4; m++) w[m] = wv0[m*32*65 + k];
#pragma unroll
                for (int a = 0; a < 4; a++)
#pragma unroll
                    for (int c = 0; c < 4; c++)
                        acc[a][c] += h[a].x*w[c].x + h[a].y*w[c].y
                                   + h[a].z*w[c].z + h[a].w*w[c].w;
            }
#pragma unroll
            for (int a = 0; a < 4; a++) {
                int le = eg + a*8;
#pragma unroll
                for (int c = 0; c < 4; c++) {
                    int o = ogr + c*32;
                    sh1[le*128 + o] = fmaxf(acc[a][c] + sb1[o], 0.f);
                }
            }
        }
        __syncthreads();
        if (tid < 64) {
            int le = tid >> 1, cls = tid & 1;
            float l = sb2v[cls];
            const float* hh = sh1 + le*128;
            const float* ww = sW2 + cls*128;
#pragma unroll 4
            for (int k = 0; k < 128; k++) l += hh[k]*ww[k];
            slog[le*2 + cls] = l;
        }
        __syncthreads();
        if (tid < nE) {
            int le = tid;
            float l0 = slog[le*2], l1 = slog[le*2 + 1];
            float mx = fmaxf(l0, l1);
            float ex0 = expf(l0 - mx), ex1 = expf(l1 - mx);
            float inv = 1.f/(ex0 + ex1);
            float p0 = ex0*inv, p1 = ex1*inv;
            float lg0 = fmaxf(logf(p0), -100.f);
            float lg1 = fmaxf(logf(p1), -100.f);
            float lm0 = fmaxf(log1pf(-p0), -100.f);
            float lm1 = fmaxf(log1pf(-p1), -100.f);
            int s = sS[le];
            const float* cp = con + (long)(base + tid)*2;
            float c0v = cp[0], c1v = cp[1];
            sbce[le*2 + 0] = -(c0v*lg0 + (1.f - c0v)*lm0);
            sbce[le*2 + 1] = -(c1v*lg1 + (1.f - c1v)*lm1);
        }
        __syncthreads();
        if (tid < 2) {
            for (int le = 0; le < nE; le++)
                sacc[sS[le]*2 + tid] += sbce[le*2 + tid];
        }
        __syncthreads();
    }
    if (tid < 64) g_part[blockIdx.x*64 + tid] = sacc[tid];
}

// ---------------- deterministic final reduction ----------------
__global__ void k_reduce(float* __restrict__ out) {
    int tid = threadIdx.x; // 64
    float a = 0.f;
    for (int b = 0; b < EBLK; b++) a += g_part[b*64 + tid];
    out[tid] = a;
}

extern "C" void kernel_launch(void* const* d_in, const int* in_sizes, int n_in,
                              void* d_out, int out_size) {
    const float* x       = (const float*)d_in[0];
    const float* con     = (const float*)d_in[1];
    const float* z_ph    = (const float*)d_in[2];
    const float* init_ph = (const float*)d_in[3];
    const float* cc_W0   = (const float*)d_in[4];
    const float* cc_b0   = (const float*)d_in[5];
    const float* cc_W1   = (const float*)d_in[6];
    const float* cc_b1   = (const float*)d_in[7];
    const float* cc_W2   = (const float*)d_in[8];
    const float* cc_b2   = (const float*)d_in[9];
    const float* er_W0   = (const float*)d_in[10];
    const float* er_b0   = (const float*)d_in[11];
    const float* er_W1   = (const float*)d_in[12];
    const float* er_b1   = (const float*)d_in[13];
    const float* er_W2   = (const float*)d_in[14];
    const float* er_b2   = (const float*)d_in[15];
    const float* rr_W    = (const float*)d_in[16];
    const float* rr_b    = (const float*)d_in[17];
    const float* dec_Wih = (const float*)d_in[18];
    const float* dec_Whh = (const float*)d_in[19];
    const float* dec_bih = (const float*)d_in[20];
    const float* dec_bhh = (const float*)d_in[21];
    const float* upd_Wih = (const float*)d_in[22];
    const float* upd_Whh = (const float*)d_in[23];
    const float* upd_bih = (const float*)d_in[24];
    const float* upd_bhh = (const float*)d_in[25];
    float* out = (float*)d_out;

    cudaFuncSetAttribute(k_recur, cudaFuncAttributeMaxDynamicSharedMemorySize, 23648*4);
    cudaFuncSetAttribute(k_edge,  cudaFuncAttributeMaxDynamicSharedMemorySize, 46404*4);

    k_init<<<32, 256>>>();
    k_c0<<<1, 256>>>(z_ph, init_ph, cc_W0, cc_b0, cc_W1, cc_b1, cc_W2, cc_b2);
    // rnninp = relu(x[:,1:] @ rr_W^T + rr_b)   (M=4064, N=256, K=516)
    k_gemm<<<dim3(4, 64), 256>>>(x, F_, 1, rr_W, F_, rr_b, g_rnninp, D_,
                                 M4, D_, F_, 1);
    // ugi = rnninp @ upd_Wih^T + upd_bih       (M=4064, N=768, K=256)
    k_gemm<<<dim3(12, 64), 256>>>(g_rnninp, D_, 0, upd_Wih, D_, upd_bih, g_ugi, 3*D_,
                                  M4, 3*D_, D_, 0);
    // persistent coupled recurrence (127 steps, 1 launch)
    k_recur<<<RBLK, 256, 23648*4>>>(upd_Whh, upd_bhh,
                                    dec_Wih, dec_bih, dec_Whh, dec_bhh);
    // P = mem @ W0a^T ; Q = mem @ W0b^T + b0   (er_W0 is (256, 512))
    k_gemm<<<dim3(4, 64), 256>>>(g_mem, D_, 0, er_W0, 2*D_, nullptr, g_P, D_,
                                 M4, D_, D_, 0);
    k_gemm<<<dim3(4, 64), 256>>>(g_mem, D_, 0, er_W0 + D_, 2*D_, er_b0, g_Q, D_,
                                 M4, D_, D_, 0);
    // edge MLP + BCE
    k_edge<<<EBLK, 256, 46404*4>>>(con, er_W1, er_b1, er_W2, er_b2);
    k_reduce<<<1, 64>>>(out);
}